// round 1
// baseline (speedup 1.0000x reference)
#include <cuda_runtime.h>

#define NFFT  4096
#define FREQ  2049
#define TPB   256
#define NBATCH 8192

// Twiddle table: g_tw[p] = exp(-2*pi*i * p / 4096), p in [0, 2048)
__device__ float2 g_tw[2048];

__global__ void tw_init_kernel() {
    int p = blockIdx.x * blockDim.x + threadIdx.x;
    if (p < 2048) {
        float s, c;
        sincospif(-(float)p * (1.0f / 2048.0f), &s, &c);  // angle = -2*pi*p/4096
        g_tw[p] = make_float2(c, s);
    }
}

__device__ __forceinline__ float2 cmul(float2 a, float2 b) {
    return make_float2(fmaf(a.x, b.x, -a.y * b.y),
                       fmaf(a.x, b.y,  a.y * b.x));
}

// One block = complex FFT of z = x[2b] + i*x[2b+1] (rows zero-padded 2049->4096),
// then unpack real spectra of both rows and scale by 0.02 (x0.5 from unpack => 0.01).
extern "C" __global__ void __launch_bounds__(TPB)
fft_energy_kernel(const float* __restrict__ x, float* __restrict__ out) {
    extern __shared__ float2 smem[];
    float2* bufA = smem;
    float2* bufB = smem + NFFT;

    const int tid = threadIdx.x;
    const int blk = blockIdx.x;
    const float* r0 = x + (size_t)(2 * blk) * FREQ;
    const float* r1 = r0 + FREQ;

    // Load packed complex input, zero-padded to 4096.
    for (int t = tid; t < NFFT; t += TPB) {
        float re = 0.0f, im = 0.0f;
        if (t < FREQ) { re = r0[t]; im = r1[t]; }
        bufA[t] = make_float2(re, im);
    }
    __syncthreads();

    // 6 radix-4 Stockham stages (out-of-place ping-pong, natural order output).
    float2* src = bufA;
    float2* dst = bufB;
#pragma unroll
    for (int stage = 0; stage < 6; stage++) {
        const int ls  = 2 * stage;
        const int l   = 1 << ls;          // 1,4,16,64,256,1024
        const int tws = 1024 >> ls;       // twiddle stride into 4096-root table
#pragma unroll
        for (int it = 0; it < NFFT / 4 / TPB; it++) {
            int j = tid + it * TPB;       // j in [0, 1024)
            int k = j & (l - 1);
            float2 a = src[j];
            float2 b = src[j + 1024];
            float2 c = src[j + 2048];
            float2 d = src[j + 3072];
            // w1 = exp(-2*pi*i*k/(4l)), w2 = w1^2, w3 = w1^3
            float2 w1 = g_tw[k * tws];
            float2 w2 = g_tw[2 * k * tws];
            float2 w3 = cmul(w1, w2);
            b = cmul(b, w1);
            c = cmul(c, w2);
            d = cmul(d, w3);
            float2 apc = make_float2(a.x + c.x, a.y + c.y);
            float2 amc = make_float2(a.x - c.x, a.y - c.y);
            float2 bpd = make_float2(b.x + d.x, b.y + d.y);
            float2 bmd = make_float2(b.x - d.x, b.y - d.y);
            int base = 4 * j - 3 * k;     // q*4l + k
            dst[base]         = make_float2(apc.x + bpd.x, apc.y + bpd.y); // a+b+c+d
            dst[base + l]     = make_float2(amc.x + bmd.y, amc.y - bmd.x); // (a-c) - i(b-d)
            dst[base + 2 * l] = make_float2(apc.x - bpd.x, apc.y - bpd.y); // (a+c) - (b+d)
            dst[base + 3 * l] = make_float2(amc.x - bmd.y, amc.y + bmd.x); // (a-c) + i(b-d)
        }
        __syncthreads();
        float2* t2 = src; src = dst; dst = t2;
    }
    // After 6 stages result is back in bufA (== src).

    // Unpack two real spectra: Re X0[k] = (Re Z[k]+Re Z[N-k])/2,
    //                          Re X1[k] = (Im Z[k]+Im Z[N-k])/2 ; scale 0.02 => 0.01.
    float* o0 = out + (size_t)(2 * blk) * NFFT;
    float* o1 = o0 + NFFT;
    for (int k = tid; k < NFFT; k += TPB) {
        float2 zk = src[k];
        float2 zn = src[(NFFT - k) & (NFFT - 1)];
        o0[k] = 0.01f * (zk.x + zn.x);
        o1[k] = 0.01f * (zk.y + zn.y);
    }
}

extern "C" void kernel_launch(void* const* d_in, const int* in_sizes, int n_in,
                              void* d_out, int out_size) {
    const float* x = (const float*)d_in[0];   // (8192, 2049) fp32; filters ignored (exact DFT identity)
    float* out = (float*)d_out;               // (8192, 4096) fp32

    // 64 KB dynamic smem (two 4096-pt complex ping-pong buffers) needs opt-in.
    // Idempotent, not a stream op: safe under graph capture, called every launch.
    cudaFuncSetAttribute(fft_energy_kernel,
                         cudaFuncAttributeMaxDynamicSharedMemorySize,
                         2 * NFFT * (int)sizeof(float2));

    tw_init_kernel<<<8, 256>>>();
    fft_energy_kernel<<<NBATCH / 2, TPB, 2 * NFFT * sizeof(float2)>>>(x, out);
}

// round 2
// speedup vs baseline: 2.7732x; 2.7732x over previous
#include <cuda_runtime.h>

#define NFFT   4096
#define FREQ   2049
#define TPB    256
#define NBATCH 8192

// g_tw[p] = exp(-2*pi*i * p / 4096), p in [0, 4096)
__device__ float2 g_tw[NFFT];

__global__ void tw_init_kernel() {
    int p = blockIdx.x * blockDim.x + threadIdx.x;
    if (p < NFFT) {
        float s, c;
        sincospif(-(float)p * (1.0f / 2048.0f), &s, &c);
        g_tw[p] = make_float2(c, s);
    }
}

__device__ __forceinline__ float2 cmul(float2 a, float2 b) {
    return make_float2(fmaf(a.x, b.x, -a.y * b.y),
                       fmaf(a.x, b.y,  a.y * b.x));
}

// In-place forward radix-4 butterfly (W4 = -i).
__device__ __forceinline__ void bf4(float2& a, float2& b, float2& c, float2& d) {
    float2 apc = make_float2(a.x + c.x, a.y + c.y);
    float2 amc = make_float2(a.x - c.x, a.y - c.y);
    float2 bpd = make_float2(b.x + d.x, b.y + d.y);
    float2 bmd = make_float2(b.x - d.x, b.y - d.y);
    a = make_float2(apc.x + bpd.x, apc.y + bpd.y);
    b = make_float2(amc.x + bmd.y, amc.y - bmd.x);   // (a-c) - i(b-d)
    c = make_float2(apc.x - bpd.x, apc.y - bpd.y);
    d = make_float2(amc.x - bmd.y, amc.y + bmd.x);   // (a-c) + i(b-d)
}

#define C_W1x  0.92387953f
#define C_W1y -0.38268343f
#define C_W2x  0.70710678f
#define C_W2y -0.70710678f

// 16-pt forward DFT over v[0..15]; output y[k] lives at v[P16(k)].
#define P16(k) ((((k) & 3) << 2) | ((k) >> 2))
__device__ __forceinline__ void fft16(float2 v[16]) {
    // stage 1: radix-4 over n2 (stride 4) for each n1; b_{n1}[k2] -> v[n1+4*k2]
    bf4(v[0], v[4], v[8],  v[12]);
    bf4(v[1], v[5], v[9],  v[13]);
    bf4(v[2], v[6], v[10], v[14]);
    bf4(v[3], v[7], v[11], v[15]);
    // W16^{n1*k2} twiddles
    const float2 W1 = make_float2(C_W1x, C_W1y);
    const float2 W2 = make_float2(C_W2x, C_W2y);
    const float2 W3 = make_float2(-C_W1y, -C_W1x);   // (sin pi/8 sign) = (0.3827,-0.9239)
    const float2 W6 = make_float2(-C_W2x, C_W2y);    // (-0.7071,-0.7071)
    const float2 W9 = make_float2(-C_W1x, -C_W1y);   // (-0.9239, 0.3827)
    v[5]  = cmul(v[5],  W1);
    v[9]  = cmul(v[9],  W2);
    v[13] = cmul(v[13], W3);
    v[6]  = cmul(v[6],  W2);
    v[10] = make_float2(v[10].y, -v[10].x);          // * -i
    v[14] = cmul(v[14], W6);
    v[7]  = cmul(v[7],  W3);
    v[11] = cmul(v[11], W6);
    v[15] = cmul(v[15], W9);
    // stage 2: radix-4 over n1 (stride 1) for each k2; y[k2+4*k1] -> v[4*k2+k1]
    bf4(v[0],  v[1],  v[2],  v[3]);
    bf4(v[4],  v[5],  v[6],  v[7]);
    bf4(v[8],  v[9],  v[10], v[11]);
    bf4(v[12], v[13], v[14], v[15]);
}

// Apply W4096^{base*k} given w1 = W^base powers: p2=w1^2,p3=w1^3, w4=W^{4base}, q2=w4^2, q3=w4^3.
__device__ __forceinline__ float2 twid(int k, float2 y,
                                       float2 w1, float2 p2, float2 p3,
                                       float2 w4, float2 q2, float2 q3) {
    const int a = k >> 2, b = k & 3;
    float2 r = y;
    if (b == 1) r = cmul(r, w1);
    else if (b == 2) r = cmul(r, p2);
    else if (b == 3) r = cmul(r, p3);
    if (a == 1) r = cmul(r, w4);
    else if (a == 2) r = cmul(r, q2);
    else if (a == 3) r = cmul(r, q3);
    return r;
}

// One block: 4096-pt complex FFT of z = x[2b] + i*x[2b+1] (zero-padded 2049->4096),
// register-resident radix-16^3, then real-pair unpack, scale 0.02*0.5 = 0.01.
extern "C" __global__ void __launch_bounds__(TPB, 3)
fft_energy_kernel(const float* __restrict__ x, float* __restrict__ out) {
    __shared__ float2 S[4112];          // max(257*16, 4096) with +1 pad layout for T1

    const int t   = threadIdx.x;
    const int blk = blockIdx.x;
    const float* r0 = x + (size_t)(2 * blk) * FREQ;
    const float* r1 = r0 + FREQ;

    float2 v[16];

    // ---- Phase A: thread m = t handles n = m + 256*j ----
    {
        const int m = t;
#pragma unroll
        for (int j = 0; j < 8; j++) {
            int idx = m + 256 * j;
            v[j] = make_float2(r0[idx], r1[idx]);
        }
        v[8] = (m == 0) ? make_float2(r0[2048], r1[2048]) : make_float2(0.f, 0.f);
#pragma unroll
        for (int j = 9; j < 16; j++) v[j] = make_float2(0.f, 0.f);

        fft16(v);   // y[k1] at v[P16(k1)]

        float2 w1 = g_tw[m];
        float2 w4 = g_tw[4 * m];
        float2 p2 = cmul(w1, w1), p3 = cmul(p2, w1);
        float2 q2 = cmul(w4, w4), q3 = cmul(q2, w4);
#pragma unroll
        for (int k1 = 0; k1 < 16; k1++)
            S[257 * k1 + m] = twid(k1, v[P16(k1)], w1, p2, p3, w4, q2, q3);
    }
    __syncthreads();

    // ---- Phase B: thread (k1 = t&15, m' = t>>4) ----
    {
        const int k1 = t & 15, mp = t >> 4;
#pragma unroll
        for (int j2 = 0; j2 < 16; j2++)
            v[j2] = S[257 * k1 + mp + 16 * j2];

        fft16(v);   // u[k2] at v[P16(k2)]

        float2 w1 = g_tw[16 * mp];
        float2 w4 = g_tw[64 * mp];
        float2 p2 = cmul(w1, w1), p3 = cmul(p2, w1);
        float2 q2 = cmul(w4, w4), q3 = cmul(q2, w4);
        __syncthreads();
#pragma unroll
        for (int k2 = 0; k2 < 16; k2++)
            S[k1 + 16 * mp + 256 * k2] = twid(k2, v[P16(k2)], w1, p2, p3, w4, q2, q3);
    }
    __syncthreads();

    // ---- Phase C: thread (k1 = t&15, k2 = t>>4) ----
    {
        const int k1 = t & 15, k2 = t >> 4;
#pragma unroll
        for (int mp = 0; mp < 16; mp++)
            v[mp] = S[k1 + 16 * mp + 256 * k2];

        fft16(v);   // Z[t + 256*k3] = v[P16(k3)]
        __syncthreads();
#pragma unroll
        for (int k3 = 0; k3 < 16; k3++)
            S[t + 256 * k3] = v[P16(k3)];
    }
    __syncthreads();

    // ---- Unpack two real spectra; coalesced global writes ----
    float* o0 = out + (size_t)(2 * blk) * NFFT;
    float* o1 = o0 + NFFT;
#pragma unroll
    for (int r = 0; r < 16; r++) {
        int k = t + 256 * r;
        float2 zk = v[P16(r)];                    // own value, still in registers
        float2 zn = S[(NFFT - k) & (NFFT - 1)];
        o0[k] = 0.01f * (zk.x + zn.x);
        o1[k] = 0.01f * (zk.y + zn.y);
    }
}

extern "C" void kernel_launch(void* const* d_in, const int* in_sizes, int n_in,
                              void* d_out, int out_size) {
    const float* x = (const float*)d_in[0];   // (8192, 2049) fp32
    float* out = (float*)d_out;               // (8192, 4096) fp32

    tw_init_kernel<<<16, 256>>>();
    fft_energy_kernel<<<NBATCH / 2, TPB>>>(x, out);
}

// round 3
// speedup vs baseline: 2.7750x; 1.0006x over previous
#include <cuda_runtime.h>

#define NFFT   4096
#define FREQ   2049
#define TPB    256
#define NBATCH 8192

__device__ __forceinline__ float2 cmul(float2 a, float2 b) {
    return make_float2(fmaf(a.x, b.x, -a.y * b.y),
                       fmaf(a.x, b.y,  a.y * b.x));
}

// In-place forward radix-4 butterfly (W4 = -i).
__device__ __forceinline__ void bf4(float2& a, float2& b, float2& c, float2& d) {
    float2 apc = make_float2(a.x + c.x, a.y + c.y);
    float2 amc = make_float2(a.x - c.x, a.y - c.y);
    float2 bpd = make_float2(b.x + d.x, b.y + d.y);
    float2 bmd = make_float2(b.x - d.x, b.y - d.y);
    a = make_float2(apc.x + bpd.x, apc.y + bpd.y);
    b = make_float2(amc.x + bmd.y, amc.y - bmd.x);   // (a-c) - i(b-d)
    c = make_float2(apc.x - bpd.x, apc.y - bpd.y);
    d = make_float2(amc.x - bmd.y, amc.y + bmd.x);   // (a-c) + i(b-d)
}

#define C_W1x  0.92387953f
#define C_W1y -0.38268343f
#define C_W2x  0.70710678f
#define C_W2y -0.70710678f

#define P16(k) ((((k) & 3) << 2) | ((k) >> 2))

// Shared tail of the 16-pt DFT: W16 twiddles + second radix-4 stage.
// On entry v holds first-stage butterfly outputs; on exit y[k] is at v[P16(k)].
__device__ __forceinline__ void fft16_tail(float2 v[16]) {
    const float2 W1 = make_float2(C_W1x, C_W1y);
    const float2 W2 = make_float2(C_W2x, C_W2y);
    const float2 W3 = make_float2(-C_W1y, -C_W1x);
    const float2 W6 = make_float2(-C_W2x, C_W2y);
    const float2 W9 = make_float2(-C_W1x, -C_W1y);
    v[5]  = cmul(v[5],  W1);
    v[9]  = cmul(v[9],  W2);
    v[13] = cmul(v[13], W3);
    v[6]  = cmul(v[6],  W2);
    v[10] = make_float2(v[10].y, -v[10].x);          // * -i
    v[14] = cmul(v[14], W6);
    v[7]  = cmul(v[7],  W3);
    v[11] = cmul(v[11], W6);
    v[15] = cmul(v[15], W9);
    bf4(v[0],  v[1],  v[2],  v[3]);
    bf4(v[4],  v[5],  v[6],  v[7]);
    bf4(v[8],  v[9],  v[10], v[11]);
    bf4(v[12], v[13], v[14], v[15]);
}

// Full 16-pt forward DFT.
__device__ __forceinline__ void fft16(float2 v[16]) {
    bf4(v[0], v[4], v[8],  v[12]);
    bf4(v[1], v[5], v[9],  v[13]);
    bf4(v[2], v[6], v[10], v[14]);
    bf4(v[3], v[7], v[11], v[15]);
    fft16_tail(v);
}

// 16-pt forward DFT with v[8..15] known zero (only v[0..7] valid on entry).
__device__ __forceinline__ void fft16_zh(float2 v[16]) {
#pragma unroll
    for (int j = 0; j < 4; j++) {
        float2 a = v[j], b = v[j + 4];
        v[j]      = make_float2(a.x + b.x, a.y + b.y);
        v[j + 4]  = make_float2(a.x + b.y, a.y - b.x);   // a - i b
        v[j + 8]  = make_float2(a.x - b.x, a.y - b.y);
        v[j + 12] = make_float2(a.x - b.y, a.y + b.x);   // a + i b
    }
    fft16_tail(v);
}

// Apply W4096^{base*k} from precomputed powers of w1 = W^base.
__device__ __forceinline__ float2 twid(int k, float2 y,
                                       float2 w1, float2 p2, float2 p3,
                                       float2 w4, float2 q2, float2 q3) {
    const int a = k >> 2, b = k & 3;
    float2 r = y;
    if (b == 1) r = cmul(r, w1);
    else if (b == 2) r = cmul(r, p2);
    else if (b == 3) r = cmul(r, p3);
    if (a == 1) r = cmul(r, w4);
    else if (a == 2) r = cmul(r, q2);
    else if (a == 3) r = cmul(r, q3);
    return r;
}

// One block: 4096-pt complex FFT of z = x[2b] + i*x[2b+1] (rows zero-padded),
// register-resident radix-16^3, x[2048] term handled analytically, then
// symmetric real-pair unpack (o[k] == o[N-k]), scale 0.02*0.5 = 0.01.
extern "C" __global__ void __launch_bounds__(TPB, 3)
fft_energy_kernel(const float* __restrict__ x, float* __restrict__ out) {
    __shared__ float2 S[4608];           // phase-A layout: S[18*m + k1] (pad 18)

    const int t   = threadIdx.x;
    const int blk = blockIdx.x;
    const float* r0 = x + (size_t)(2 * blk) * FREQ;
    const float* r1 = r0 + FREQ;

    // Broadcast load of the n=2048 sample (handled outside the FFT).
    const float2 c2 = make_float2(r0[2048], r1[2048]);

    float2 v[16];

    // ---- Phase A: thread m handles n = m + 256*j, j<8 (rest zero) ----
    {
        const int m = t;
#pragma unroll
        for (int j = 0; j < 8; j++) {
            int idx = m + 256 * j;
            v[j] = make_float2(r0[idx], r1[idx]);
        }
        fft16_zh(v);     // y[k1] at v[P16(k1)]

        float s1, c1;
        sincospif(-(float)m * (1.0f / 2048.0f), &s1, &c1);  // W4096^m
        float2 w1 = make_float2(c1, s1);
        float2 p2 = cmul(w1, w1), p3 = cmul(p2, w1);
        float2 w4 = cmul(p2, p2);
        float2 q2 = cmul(w4, w4), q3 = cmul(q2, w4);
#pragma unroll
        for (int k1 = 0; k1 < 16; k1 += 2) {
            float2 e = twid(k1,     v[P16(k1)],     w1, p2, p3, w4, q2, q3);
            float2 o = twid(k1 + 1, v[P16(k1 + 1)], w1, p2, p3, w4, q2, q3);
            *reinterpret_cast<float4*>(&S[18 * m + k1]) =
                make_float4(e.x, e.y, o.x, o.y);              // STS.128, CF
        }
    }
    __syncthreads();

    // ---- Phase B: thread (k1 = t&15, m' = t>>4) ----
    {
        const int k1 = t & 15, mp = t >> 4;
#pragma unroll
        for (int j2 = 0; j2 < 16; j2++)
            v[j2] = S[18 * (mp + 16 * j2) + k1];

        fft16(v);        // u[k2] at v[P16(k2)]

        float sb, cb;
        sincospif(-(float)mp * (1.0f / 128.0f), &sb, &cb);    // W4096^{16 m'}
        float2 w1 = make_float2(cb, sb);
        float2 p2 = cmul(w1, w1), p3 = cmul(p2, w1);
        float2 w4 = cmul(p2, p2);
        float2 q2 = cmul(w4, w4), q3 = cmul(q2, w4);
        __syncthreads();
#pragma unroll
        for (int k2 = 0; k2 < 16; k2++)
            S[t + 256 * k2] = twid(k2, v[P16(k2)], w1, p2, p3, w4, q2, q3);
    }
    __syncthreads();

    // ---- Phase C: thread (k1 = t&15, k2 = t>>4) ----
    {
        const int k1 = t & 15, k2 = t >> 4;
#pragma unroll
        for (int mp = 0; mp < 16; mp++)
            v[mp] = S[k1 + 16 * mp + 256 * k2];

        fft16(v);        // Z[t + 256*k3] = v[P16(k3)]
        __syncthreads();
#pragma unroll
        for (int k3 = 0; k3 < 16; k3++)
            S[t + 256 * k3] = v[P16(k3)];
    }
    __syncthreads();

    // ---- Symmetric unpack: o[k] = o[4096-k]. Compute k in [0,2048], write both.
    // Correction for the n=2048 input term: Z_full[k] = Z[k] + c2*(-1)^k, so
    // zk + z(N-k) gets +2*c2*(-1)^k.
    float* o0 = out + (size_t)(2 * blk) * NFFT;
    float* o1 = o0 + NFFT;
#pragma unroll
    for (int r = 0; r < 4; r++) {
        int k = 2 * t + 512 * r;                       // even, in [0, 2046]
        float4 own = *reinterpret_cast<const float4*>(&S[k]);   // Z[k], Z[k+1]
        float2 ma = S[k == 0 ? 0 : 4096 - k];          // Z[N-k]
        float2 mb = S[4095 - k];                       // Z[N-k-1]
        float o0a = 0.01f * (own.x + ma.x + 2.0f * c2.x);
        float o1a = 0.01f * (own.y + ma.y + 2.0f * c2.y);
        float o0b = 0.01f * (own.z + mb.x - 2.0f * c2.x);
        float o1b = 0.01f * (own.w + mb.y - 2.0f * c2.y);
        *reinterpret_cast<float2*>(&o0[k]) = make_float2(o0a, o0b);
        *reinterpret_cast<float2*>(&o1[k]) = make_float2(o1a, o1b);
        if (k != 0) {
            // mirror pair (4095-k, 4096-k) = values (o?b, o?a); 4095-k is odd,
            // so these are scalar stores (float2 would be misaligned).
            o0[4095 - k] = o0b;  o0[4096 - k] = o0a;
            o1[4095 - k] = o1b;  o1[4096 - k] = o1a;
        } else {
            o0[4095] = o0b;  o1[4095] = o1b;           // mirror of k=1 only
        }
    }
    if (t == 0) {                                      // k = 2048 self-mirror
        float2 z = S[2048];
        o0[2048] = 0.01f * (2.0f * z.x + 2.0f * c2.x);
        o1[2048] = 0.01f * (2.0f * z.y + 2.0f * c2.y);
    }
}

extern "C" void kernel_launch(void* const* d_in, const int* in_sizes, int n_in,
                              void* d_out, int out_size) {
    const float* x = (const float*)d_in[0];   // (8192, 2049) fp32
    float* out = (float*)d_out;               // (8192, 4096) fp32
    fft_energy_kernel<<<NBATCH / 2, TPB>>>(x, out);
}

// round 4
// speedup vs baseline: 3.0056x; 1.0831x over previous
#include <cuda_runtime.h>

#define NFFT   4096
#define FREQ   2049
#define TPB    256
#define NBATCH 8192

__device__ __forceinline__ float2 cmul(float2 a, float2 b) {
    return make_float2(fmaf(a.x, b.x, -a.y * b.y),
                       fmaf(a.x, b.y,  a.y * b.x));
}

// In-place forward radix-4 butterfly (W4 = -i).
__device__ __forceinline__ void bf4(float2& a, float2& b, float2& c, float2& d) {
    float2 apc = make_float2(a.x + c.x, a.y + c.y);
    float2 amc = make_float2(a.x - c.x, a.y - c.y);
    float2 bpd = make_float2(b.x + d.x, b.y + d.y);
    float2 bmd = make_float2(b.x - d.x, b.y - d.y);
    a = make_float2(apc.x + bpd.x, apc.y + bpd.y);
    b = make_float2(amc.x + bmd.y, amc.y - bmd.x);   // (a-c) - i(b-d)
    c = make_float2(apc.x - bpd.x, apc.y - bpd.y);
    d = make_float2(amc.x - bmd.y, amc.y + bmd.x);   // (a-c) + i(b-d)
}

#define C_W1x  0.92387953f
#define C_W1y -0.38268343f
#define C_W2x  0.70710678f
#define C_W2y -0.70710678f

#define P16(k) ((((k) & 3) << 2) | ((k) >> 2))

// Shared tail of the 16-pt DFT: W16 twiddles + second radix-4 stage.
__device__ __forceinline__ void fft16_tail(float2 v[16]) {
    const float2 W1 = make_float2(C_W1x, C_W1y);
    const float2 W2 = make_float2(C_W2x, C_W2y);
    const float2 W3 = make_float2(-C_W1y, -C_W1x);
    const float2 W6 = make_float2(-C_W2x, C_W2y);
    const float2 W9 = make_float2(-C_W1x, -C_W1y);
    v[5]  = cmul(v[5],  W1);
    v[9]  = cmul(v[9],  W2);
    v[13] = cmul(v[13], W3);
    v[6]  = cmul(v[6],  W2);
    v[10] = make_float2(v[10].y, -v[10].x);          // * -i
    v[14] = cmul(v[14], W6);
    v[7]  = cmul(v[7],  W3);
    v[11] = cmul(v[11], W6);
    v[15] = cmul(v[15], W9);
    bf4(v[0],  v[1],  v[2],  v[3]);
    bf4(v[4],  v[5],  v[6],  v[7]);
    bf4(v[8],  v[9],  v[10], v[11]);
    bf4(v[12], v[13], v[14], v[15]);
}

__device__ __forceinline__ void fft16(float2 v[16]) {
    bf4(v[0], v[4], v[8],  v[12]);
    bf4(v[1], v[5], v[9],  v[13]);
    bf4(v[2], v[6], v[10], v[14]);
    bf4(v[3], v[7], v[11], v[15]);
    fft16_tail(v);
}

// 16-pt DFT with v[8..15] known zero (only v[0..7] valid on entry).
__device__ __forceinline__ void fft16_zh(float2 v[16]) {
#pragma unroll
    for (int j = 0; j < 4; j++) {
        float2 a = v[j], b = v[j + 4];
        v[j]      = make_float2(a.x + b.x, a.y + b.y);
        v[j + 4]  = make_float2(a.x + b.y, a.y - b.x);   // a - i b
        v[j + 8]  = make_float2(a.x - b.x, a.y - b.y);
        v[j + 12] = make_float2(a.x - b.y, a.y + b.x);   // a + i b
    }
    fft16_tail(v);
}

// Apply W4096^{base*k} from precomputed powers of w1 = W^base.
__device__ __forceinline__ float2 twid(int k, float2 y,
                                       float2 w1, float2 p2, float2 p3,
                                       float2 w4, float2 q2, float2 q3) {
    const int a = k >> 2, b = k & 3;
    float2 r = y;
    if (b == 1) r = cmul(r, w1);
    else if (b == 2) r = cmul(r, p2);
    else if (b == 3) r = cmul(r, p3);
    if (a == 1) r = cmul(r, w4);
    else if (a == 2) r = cmul(r, q2);
    else if (a == 3) r = cmul(r, q3);
    return r;
}

// One block: 4096-pt complex FFT of z = x[2b] + i*x[2b+1] (zero-padded),
// register radix-16^3. Phase-C columns assigned so mirror column 256-c is the
// xor-16 lane partner -> unpack via warp shuffle, no 3rd smem pass.
extern "C" __global__ void __launch_bounds__(TPB, 3)
fft_energy_kernel(const float* __restrict__ x, float* __restrict__ out) {
    __shared__ float2 S[4608];           // phase-A layout: S[18*m + k1]

    const int t    = threadIdx.x;
    const int lane = t & 31;
    const int wrp  = t >> 5;
    const int blk  = blockIdx.x;
    const float* r0 = x + (size_t)(2 * blk) * FREQ;
    const float* r1 = r0 + FREQ;

    // n=2048 sample handled analytically outside the FFT.
    const float2 c2 = make_float2(r0[2048], r1[2048]);

    float2 v[16];

    // ---- Phase A: thread m handles n = m + 256*j, j<8 (rest zero) ----
    {
        const int m = t;
#pragma unroll
        for (int j = 0; j < 8; j++) {
            int idx = m + 256 * j;
            v[j] = make_float2(r0[idx], r1[idx]);
        }
        fft16_zh(v);     // y[k1] at v[P16(k1)]

        float s1, c1;
        sincospif(-(float)m * (1.0f / 2048.0f), &s1, &c1);  // W4096^m
        float2 w1 = make_float2(c1, s1);
        float2 p2 = cmul(w1, w1), p3 = cmul(p2, w1);
        float2 w4 = cmul(p2, p2);
        float2 q2 = cmul(w4, w4), q3 = cmul(q2, w4);
#pragma unroll
        for (int k1 = 0; k1 < 16; k1 += 2) {
            float2 e = twid(k1,     v[P16(k1)],     w1, p2, p3, w4, q2, q3);
            float2 o = twid(k1 + 1, v[P16(k1 + 1)], w1, p2, p3, w4, q2, q3);
            *reinterpret_cast<float4*>(&S[18 * m + k1]) =
                make_float4(e.x, e.y, o.x, o.y);
        }
    }
    __syncthreads();

    // ---- Phase B: thread (k1 = t&15, m' = t>>4) ----
    {
        const int k1 = t & 15, mp = t >> 4;
#pragma unroll
        for (int j2 = 0; j2 < 16; j2++)
            v[j2] = S[18 * (mp + 16 * j2) + k1];

        fft16(v);        // u[k2] at v[P16(k2)]

        float sb, cb;
        sincospif(-(float)mp * (1.0f / 128.0f), &sb, &cb);    // W4096^{16 m'}
        float2 w1 = make_float2(cb, sb);
        float2 p2 = cmul(w1, w1), p3 = cmul(p2, w1);
        float2 w4 = cmul(p2, p2);
        float2 q2 = cmul(w4, w4), q3 = cmul(q2, w4);
        __syncthreads();
#pragma unroll
        for (int k2 = 0; k2 < 16; k2++)
            S[t + 256 * k2] = twid(k2, v[P16(k2)], w1, p2, p3, w4, q2, q3);
    }
    __syncthreads();

    // ---- Phase C: mirror-paired column assignment ----
    // warp w: lanes 0..15 -> c = 16w+1+lane; lanes 16..31 -> c = 271-16w-lane
    // (partner 256-c sits at lane^16). Warp 7 lane 31 overridden to c=0.
    // Self-mirror columns: c=0 (w7,l31), c=128 (w7,l15).
    {
        int c = (lane < 16) ? (16 * wrp + 1 + lane) : (271 - 16 * wrp - lane);
        const bool self0   = (wrp == 7) && (lane == 31);
        const bool self128 = (c == 128);
        if (self0) c = 0;
        const int k1 = c & 15, k2 = c >> 4;

#pragma unroll
        for (int mp = 0; mp < 16; mp++)
            v[mp] = S[k1 + 16 * mp + 256 * k2];

        fft16(v);        // Z[c + 256*k3] = v[P16(k3)]

        // Unpack + write directly from registers.
        float* o0 = out + (size_t)(2 * blk) * NFFT;
        float* o1 = o0 + NFFT;
        const float sgn = (c & 1) ? -1.0f : 1.0f;         // (-1)^n = (-1)^c
        const float a0 = 2.0f * sgn * c2.x;
        const float a1 = 2.0f * sgn * c2.y;
#pragma unroll
        for (int k3 = 0; k3 < 16; k3++) {
            float2 zk = v[P16(k3)];
            float2 zs = v[P16(15 - k3)];
            float2 zr;
            zr.x = __shfl_xor_sync(0xffffffffu, zs.x, 16);
            zr.y = __shfl_xor_sync(0xffffffffu, zs.y, 16);
            if (self128) zr = zs;                          // own col, k3'=15-k3
            if (self0)   zr = v[P16((16 - k3) & 15)];      // own col, k3'=(16-k3)&15
            int n = c + 256 * k3;
            o0[n] = 0.01f * (zk.x + zr.x + a0);
            o1[n] = 0.01f * (zk.y + zr.y + a1);
        }
    }
}

extern "C" void kernel_launch(void* const* d_in, const int* in_sizes, int n_in,
                              void* d_out, int out_size) {
    const float* x = (const float*)d_in[0];   // (8192, 2049) fp32
    float* out = (float*)d_out;               // (8192, 4096) fp32
    fft_energy_kernel<<<NBATCH / 2, TPB>>>(x, out);
}

// round 5
// speedup vs baseline: 3.0225x; 1.0056x over previous
#include <cuda_runtime.h>
#include <cstring>

#define NFFT   4096
#define FREQ   2049
#define TPB    256
#define NBATCH 8192

typedef unsigned long long ull;

// ---- packed f32x2 helpers (sm_100+ PTX; ptxas never emits these from C) ----
__device__ __forceinline__ ull pk(float x, float y) {
    ull r; asm("mov.b64 %0,{%1,%2};" : "=l"(r) : "f"(x), "f"(y)); return r;
}
__device__ __forceinline__ void upk(ull u, float& x, float& y) {
    asm("mov.b64 {%0,%1},%2;" : "=f"(x), "=f"(y) : "l"(u));
}
__device__ __forceinline__ ull padd(ull a, ull b) {
    ull r; asm("add.rn.f32x2 %0,%1,%2;" : "=l"(r) : "l"(a), "l"(b)); return r;
}
__device__ __forceinline__ ull pfma(ull a, ull b, ull c) {
    ull r; asm("fma.rn.f32x2 %0,%1,%2,%3;" : "=l"(r) : "l"(a), "l"(b), "l"(c)); return r;
}
__device__ __forceinline__ ull pmul(ull a, ull b) {
    ull r; asm("mul.rn.f32x2 %0,%1,%2;" : "=l"(r) : "l"(a), "l"(b)); return r;
}

// sign-pair constants (lo word = .x)
#define NEG1 0xBF800000BF800000ULL   /* (-1,-1) */
#define C1M1 0xBF8000003F800000ULL   /* (+1,-1) */
#define M1P1 0x3F800000BF800000ULL   /* (-1,+1) */

__device__ __forceinline__ ull pswap(ull u) {
    float x, y; upk(u, x, y); return pk(y, x);
}
// csub(a,b) = a - b  (exact: mul by -1 then single-rounded add)
__device__ __forceinline__ ull psub(ull a, ull b) { return pfma(b, NEG1, a); }

// complex mul by constant (scalar sandwich; ptxas folds the movs)
__device__ __forceinline__ ull cmulc(ull vu, float wx, float wy) {
    float x, y; upk(vu, x, y);
    return pk(fmaf(x, wx, -y * wy), fmaf(x, wy, y * wx));
}
// v * (-i) = (y, -x)
__device__ __forceinline__ ull pmneg_i(ull vu) {
    float x, y; upk(vu, x, y); return pk(y, -x);
}

// In-place packed radix-4 butterfly (W4 = -i). Bit-identical to scalar version.
__device__ __forceinline__ void bf4p(ull& a, ull& b, ull& c, ull& d) {
    ull apc = padd(a, c);
    ull amc = psub(a, c);
    ull bpd = padd(b, d);
    ull bmd = psub(b, d);
    a = padd(apc, bpd);
    c = psub(apc, bpd);
    ull sw = pswap(bmd);            // (bmd.y, bmd.x)
    b = pfma(sw, C1M1, amc);        // amc + (bmd.y, -bmd.x)  = (a-c) - i(b-d)
    d = pfma(sw, M1P1, amc);        // amc + (-bmd.y, bmd.x)  = (a-c) + i(b-d)
}

#define C_W1x  0.92387953f
#define C_W1y -0.38268343f
#define C_W2x  0.70710678f
#define C_W2y -0.70710678f

#define P16(k) ((((k) & 3) << 2) | ((k) >> 2))

// Tail: W16 twiddles + second radix-4 stage. Output y[k] at v[P16(k)].
__device__ __forceinline__ void fft16_tailp(ull v[16]) {
    v[5]  = cmulc(v[5],   C_W1x,  C_W1y);
    v[9]  = cmulc(v[9],   C_W2x,  C_W2y);
    v[13] = cmulc(v[13],  0.38268343f, -0.92387953f);   // W3
    v[6]  = cmulc(v[6],   C_W2x,  C_W2y);
    v[10] = pmneg_i(v[10]);
    v[14] = cmulc(v[14], -C_W2x,  C_W2y);               // W6
    v[7]  = cmulc(v[7],   0.38268343f, -0.92387953f);
    v[11] = cmulc(v[11], -C_W2x,  C_W2y);
    v[15] = cmulc(v[15], -C_W1x, -C_W1y);               // W9
    bf4p(v[0],  v[1],  v[2],  v[3]);
    bf4p(v[4],  v[5],  v[6],  v[7]);
    bf4p(v[8],  v[9],  v[10], v[11]);
    bf4p(v[12], v[13], v[14], v[15]);
}

__device__ __forceinline__ void fft16p(ull v[16]) {
    bf4p(v[0], v[4], v[8],  v[12]);
    bf4p(v[1], v[5], v[9],  v[13]);
    bf4p(v[2], v[6], v[10], v[14]);
    bf4p(v[3], v[7], v[11], v[15]);
    fft16_tailp(v);
}

// 16-pt DFT with v[8..15] known zero (only v[0..7] valid on entry).
__device__ __forceinline__ void fft16_zhp(ull v[16]) {
#pragma unroll
    for (int j = 0; j < 4; j++) {
        ull a = v[j], b = v[j + 4];
        ull s = pmul(pswap(b), C1M1);   // (b.y, -b.x)
        v[j]      = padd(a, b);
        v[j + 4]  = padd(a, s);         // a - i b
        v[j + 8]  = psub(a, b);
        v[j + 12] = psub(a, s);         // a + i b
    }
    fft16_tailp(v);
}

// Apply W4096^{base*k}; w powers passed as scalar float2s. Returns packed.
__device__ __forceinline__ float2 cmul2(float2 a, float2 b) {
    return make_float2(fmaf(a.x, b.x, -a.y * b.y),
                       fmaf(a.x, b.y,  a.y * b.x));
}
__device__ __forceinline__ ull twidp(int k, ull yu,
                                     float2 w1, float2 p2, float2 p3,
                                     float2 w4, float2 q2, float2 q3) {
    const int a = k >> 2, b = k & 3;
    float2 r; upk(yu, r.x, r.y);
    if (b == 1) r = cmul2(r, w1);
    else if (b == 2) r = cmul2(r, p2);
    else if (b == 3) r = cmul2(r, p3);
    if (a == 1) r = cmul2(r, w4);
    else if (a == 2) r = cmul2(r, q2);
    else if (a == 3) r = cmul2(r, q3);
    return pk(r.x, r.y);
}

// One block: 4096-pt complex FFT of z = x[2b] + i*x[2b+1] (zero-padded),
// packed-f32x2 register radix-16^3, shuffle-mirrored unpack.
extern "C" __global__ void __launch_bounds__(TPB, 4)
fft_energy_kernel(const float* __restrict__ x, float* __restrict__ out) {
    __shared__ ull S[4608];              // phase-A layout: S[18*m + k1]

    const int t    = threadIdx.x;
    const int lane = t & 31;
    const int wrp  = t >> 5;
    const int blk  = blockIdx.x;
    const float* r0 = x + (size_t)(2 * blk) * FREQ;
    const float* r1 = r0 + FREQ;

    const float2 c2 = make_float2(r0[2048], r1[2048]);   // n=2048, handled analytically

    ull v[16];

    // ---- Phase A: thread m handles n = m + 256*j, j<8 (rest zero) ----
    {
        const int m = t;
#pragma unroll
        for (int j = 0; j < 8; j++) {
            int idx = m + 256 * j;
            v[j] = pk(r0[idx], r1[idx]);
        }
        fft16_zhp(v);    // y[k1] at v[P16(k1)]

        float s1, c1;
        sincospif(-(float)m * (1.0f / 2048.0f), &s1, &c1);  // W4096^m
        float2 w1 = make_float2(c1, s1);
        float2 p2 = cmul2(w1, w1), p3 = cmul2(p2, w1);
        float2 w4 = cmul2(p2, p2);
        float2 q2 = cmul2(w4, w4), q3 = cmul2(q2, w4);
#pragma unroll
        for (int k1 = 0; k1 < 16; k1 += 2) {
            ull e = twidp(k1,     v[P16(k1)],     w1, p2, p3, w4, q2, q3);
            ull o = twidp(k1 + 1, v[P16(k1 + 1)], w1, p2, p3, w4, q2, q3);
            *reinterpret_cast<ulonglong2*>(&S[18 * m + k1]) = make_ulonglong2(e, o);
        }
    }
    __syncthreads();

    // ---- Phase B: thread (k1 = t&15, m' = t>>4) ----
    {
        const int k1 = t & 15, mp = t >> 4;
#pragma unroll
        for (int j2 = 0; j2 < 16; j2++)
            v[j2] = S[18 * (mp + 16 * j2) + k1];

        fft16p(v);       // u[k2] at v[P16(k2)]

        float sb, cb;
        sincospif(-(float)mp * (1.0f / 128.0f), &sb, &cb);    // W4096^{16 m'}
        float2 w1 = make_float2(cb, sb);
        float2 p2 = cmul2(w1, w1), p3 = cmul2(p2, w1);
        float2 w4 = cmul2(p2, p2);
        float2 q2 = cmul2(w4, w4), q3 = cmul2(q2, w4);
        __syncthreads();
#pragma unroll
        for (int k2 = 0; k2 < 16; k2++)
            S[t + 256 * k2] = twidp(k2, v[P16(k2)], w1, p2, p3, w4, q2, q3);
    }
    __syncthreads();

    // ---- Phase C: mirror-paired column assignment ----
    // warp w: lanes 0..15 -> c = 16w+1+lane; lanes 16..31 -> c = 271-16w-lane
    // (mirror column 256-c sits at lane^16). Warp 7 lane 31 overridden to c=0.
    {
        int c = (lane < 16) ? (16 * wrp + 1 + lane) : (271 - 16 * wrp - lane);
        const bool self0   = (wrp == 7) && (lane == 31);
        const bool self128 = (c == 128);
        if (self0) c = 0;
        const int k1 = c & 15, k2 = c >> 4;

#pragma unroll
        for (int mp = 0; mp < 16; mp++)
            v[mp] = S[k1 + 16 * mp + 256 * k2];

        fft16p(v);       // Z[c + 256*k3] = v[P16(k3)]

        float* o0 = out + (size_t)(2 * blk) * NFFT;
        float* o1 = o0 + NFFT;
        const float sgn = (c & 1) ? -1.0f : 1.0f;
        const float b0 = 0.02f * sgn * c2.x;     // folded: 0.01*(.. + 2*sgn*c2)
        const float b1 = 0.02f * sgn * c2.y;
#pragma unroll
        for (int k3 = 0; k3 < 16; k3++) {
            ull zk = v[P16(k3)];
            ull zs = v[P16(15 - k3)];
            float sx, sy; upk(zs, sx, sy);
            float rx = __shfl_xor_sync(0xffffffffu, sx, 16);
            float ry = __shfl_xor_sync(0xffffffffu, sy, 16);
            ull zr = pk(rx, ry);
            if (self128) zr = zs;                          // own col, k3'=15-k3
            if (self0)   zr = v[P16((16 - k3) & 15)];      // own col, k3'=(16-k3)&15
            ull s = padd(zk, zr);
            float ox, oy; upk(s, ox, oy);
            int n = c + 256 * k3;
            o0[n] = fmaf(0.01f, ox, b0);
            o1[n] = fmaf(0.01f, oy, b1);
        }
    }
}

extern "C" void kernel_launch(void* const* d_in, const int* in_sizes, int n_in,
                              void* d_out, int out_size) {
    const float* x = (const float*)d_in[0];   // (8192, 2049) fp32
    float* out = (float*)d_out;               // (8192, 4096) fp32
    fft_energy_kernel<<<NBATCH / 2, TPB>>>(x, out);
}